// round 1
// baseline (speedup 1.0000x reference)
#include <cuda_runtime.h>
#include <math.h>

// ---------------- problem constants ----------------
#define B_SZ   4
#define LEN    4096
#define HID    1024
#define STATE  16
#define KCONV  4
#define INNER  2048
#define M_TOT  (B_SZ * LEN)      // 16384
#define NC     16                // scan chunks
#define LC     256               // chunk length (NC*LC == LEN)

// ---------------- scratch (no cudaMalloc allowed) ----------------
__device__ float g_xz   [(size_t)M_TOT * 2 * INNER];   // in-proj output (x_part | z)
__device__ float g_xconv[(size_t)M_TOT * INNER];       // conv+silu output
__device__ float g_dt   [(size_t)M_TOT * INNER];       // softplus(dt)
__device__ float g_Bm   [(size_t)M_TOT * STATE];
__device__ float g_Cm   [(size_t)M_TOT * STATE];
__device__ float g_y    [(size_t)M_TOT * INNER];       // gated scan output
__device__ float g_P    [(size_t)B_SZ * NC * STATE * INNER];
__device__ float g_S    [(size_t)B_SZ * NC * STATE * INNER];
__device__ float g_H0   [(size_t)B_SZ * NC * STATE * INNER];

// ---------------- helpers ----------------
__device__ __forceinline__ float2 ffma2(float2 a, float2 b, float2 c) {
    float2 d;
    asm("fma.rn.f32x2 %0, %1, %2, %3;"
        : "=l"(*reinterpret_cast<unsigned long long*>(&d))
        : "l"(*reinterpret_cast<unsigned long long*>(&a)),
          "l"(*reinterpret_cast<unsigned long long*>(&b)),
          "l"(*reinterpret_cast<unsigned long long*>(&c)));
    return d;
}
__device__ __forceinline__ float2 dup2(float a) {
    float2 d;
    asm("mov.b64 %0, {%1, %1};"
        : "=l"(*reinterpret_cast<unsigned long long*>(&d)) : "f"(a));
    return d;
}
__device__ __forceinline__ float softplusf(float v) {
    return v > 20.f ? v : log1pf(__expf(v));
}
__device__ __forceinline__ float siluf(float v) {
    return v / (1.f + __expf(-v));
}

// ---------------- generic NT SGEMM: C[M,N] = A[M,K] * Bw[N,K]^T + bias ----------------
// EPI: 0 = bias, 1 = bias + softplus
template <int EPI>
__global__ void __launch_bounds__(256, 2) sgemm_nt(
    const float* __restrict__ A, const float* __restrict__ Bw,
    const float* __restrict__ bias, float* __restrict__ C,
    int M, int N, int Kd)
{
    const int BM = 128, BN = 128, BK = 16;
    __shared__ float As[2][BK][BM];
    __shared__ float Bs[2][BK][BN];

    const int tid  = threadIdx.x;
    const int bm   = blockIdx.y * BM;
    const int bn   = blockIdx.x * BN;
    const int lrow = tid & 127;
    const int lkv  = tid >> 7;       // 0/1
    const int tx   = tid & 15;
    const int ty   = tid >> 4;
    const int K4   = Kd >> 2;
    const float4* A4 = reinterpret_cast<const float4*>(A);
    const float4* B4 = reinterpret_cast<const float4*>(Bw);

    float2 acc[8][4];
#pragma unroll
    for (int i = 0; i < 8; i++)
#pragma unroll
        for (int j = 0; j < 4; j++) acc[i][j] = make_float2(0.f, 0.f);

    float4 ra[2], rb[2];
#pragma unroll
    for (int i = 0; i < 2; i++) {
        ra[i] = A4[(size_t)(bm + lrow) * K4 + (lkv + 2 * i)];
        rb[i] = B4[(size_t)(bn + lrow) * K4 + (lkv + 2 * i)];
    }
#pragma unroll
    for (int i = 0; i < 2; i++) {
        int kv = lkv + 2 * i;
        As[0][kv * 4 + 0][lrow] = ra[i].x; As[0][kv * 4 + 1][lrow] = ra[i].y;
        As[0][kv * 4 + 2][lrow] = ra[i].z; As[0][kv * 4 + 3][lrow] = ra[i].w;
        Bs[0][kv * 4 + 0][lrow] = rb[i].x; Bs[0][kv * 4 + 1][lrow] = rb[i].y;
        Bs[0][kv * 4 + 2][lrow] = rb[i].z; Bs[0][kv * 4 + 3][lrow] = rb[i].w;
    }
    __syncthreads();

    const int KT = Kd / BK;
    int buf = 0;
    for (int kt = 0; kt < KT; ++kt) {
        if (kt + 1 < KT) {
#pragma unroll
            for (int i = 0; i < 2; i++) {
                ra[i] = A4[(size_t)(bm + lrow) * K4 + (kt + 1) * 4 + (lkv + 2 * i)];
                rb[i] = B4[(size_t)(bn + lrow) * K4 + (kt + 1) * 4 + (lkv + 2 * i)];
            }
        }
#pragma unroll
        for (int k = 0; k < BK; k++) {
            float4 a0 = *(const float4*)&As[buf][k][ty * 4];
            float4 a1 = *(const float4*)&As[buf][k][64 + ty * 4];
            float4 b0 = *(const float4*)&Bs[buf][k][tx * 4];
            float4 b1 = *(const float4*)&Bs[buf][k][64 + tx * 4];
            float  av[8] = {a0.x, a0.y, a0.z, a0.w, a1.x, a1.y, a1.z, a1.w};
            float2 bv[4] = {make_float2(b0.x, b0.y), make_float2(b0.z, b0.w),
                            make_float2(b1.x, b1.y), make_float2(b1.z, b1.w)};
#pragma unroll
            for (int i = 0; i < 8; i++) {
                float2 aa = dup2(av[i]);
#pragma unroll
                for (int j = 0; j < 4; j++) acc[i][j] = ffma2(aa, bv[j], acc[i][j]);
            }
        }
        if (kt + 1 < KT) {
            int nb = buf ^ 1;
#pragma unroll
            for (int i = 0; i < 2; i++) {
                int kv = lkv + 2 * i;
                As[nb][kv * 4 + 0][lrow] = ra[i].x; As[nb][kv * 4 + 1][lrow] = ra[i].y;
                As[nb][kv * 4 + 2][lrow] = ra[i].z; As[nb][kv * 4 + 3][lrow] = ra[i].w;
                Bs[nb][kv * 4 + 0][lrow] = rb[i].x; Bs[nb][kv * 4 + 1][lrow] = rb[i].y;
                Bs[nb][kv * 4 + 2][lrow] = rb[i].z; Bs[nb][kv * 4 + 3][lrow] = rb[i].w;
            }
            __syncthreads();
            buf = nb;
        }
    }

    // epilogue
#pragma unroll
    for (int i = 0; i < 8; i++) {
        int row = bm + ((i < 4) ? (ty * 4 + i) : (64 + ty * 4 + (i - 4)));
#pragma unroll
        for (int j = 0; j < 4; j++) {
            int col = bn + ((j < 2) ? (tx * 4 + j * 2) : (64 + tx * 4 + (j - 2) * 2));
            float v0 = acc[i][j].x + bias[col];
            float v1 = acc[i][j].y + bias[col + 1];
            if (EPI == 1) { v0 = softplusf(v0); v1 = softplusf(v1); }
            *reinterpret_cast<float2*>(&C[(size_t)row * N + col]) = make_float2(v0, v1);
        }
    }
}

// ---------------- causal depthwise conv (K=4) + SiLU ----------------
// grid (INNER/256, LEN/128, B), block 256
__global__ void __launch_bounds__(256) conv_silu_kernel(
    const float* __restrict__ conv_w, const float* __restrict__ conv_b)
{
    const int d  = blockIdx.x * 256 + threadIdx.x;
    const int l0 = blockIdx.y * 128;
    const int b  = blockIdx.z;

    const float w0 = conv_w[d * 4 + 0];
    const float w1 = conv_w[d * 4 + 1];
    const float w2 = conv_w[d * 4 + 2];
    const float w3 = conv_w[d * 4 + 3];
    const float cb = conv_b[d];

    const float* xp = g_xz + (size_t)(b * LEN) * (2 * INNER) + d;   // x_part column d
    float m3, m2, m1;
    if (l0 == 0) { m3 = m2 = m1 = 0.f; }
    else {
        m3 = xp[(size_t)(l0 - 3) * (2 * INNER)];
        m2 = xp[(size_t)(l0 - 2) * (2 * INNER)];
        m1 = xp[(size_t)(l0 - 1) * (2 * INNER)];
    }
    float* xc = g_xconv + (size_t)(b * LEN + l0) * INNER + d;
#pragma unroll 4
    for (int i = 0; i < 128; ++i) {
        float cur = xp[(size_t)(l0 + i) * (2 * INNER)];
        float v = w0 * m3 + w1 * m2 + w2 * m1 + w3 * cur + cb;
        xc[(size_t)i * INNER] = siluf(v);
        m3 = m2; m2 = m1; m1 = cur;
    }
}

// ---------------- B/C projection: [M,32] = xconv[M,2048] @ [Bw;Cw]^T ----------------
// grid M/32, block 256
__global__ void __launch_bounds__(256) bc_gemm(
    const float* __restrict__ Bw, const float* __restrict__ Cw,
    const float* __restrict__ Bb, const float* __restrict__ Cb)
{
    __shared__ float As[32][65];
    __shared__ float Ws[32][65];
    const int tid = threadIdx.x;
    const int m0  = blockIdx.x * 32;
    const int r   = tid >> 3;          // row 0..31
    const int og  = (tid & 7) * 4;     // out base 0..28

    float acc0 = 0.f, acc1 = 0.f, acc2 = 0.f, acc3 = 0.f;
    for (int kc = 0; kc < INNER / 64; ++kc) {
        for (int i = tid; i < 32 * 64; i += 256)
            As[i >> 6][i & 63] = g_xconv[(size_t)(m0 + (i >> 6)) * INNER + kc * 64 + (i & 63)];
        for (int i = tid; i < 16 * 64; i += 256) {
            Ws[i >> 6][i & 63]        = Bw[(size_t)(i >> 6) * INNER + kc * 64 + (i & 63)];
            Ws[16 + (i >> 6)][i & 63] = Cw[(size_t)(i >> 6) * INNER + kc * 64 + (i & 63)];
        }
        __syncthreads();
#pragma unroll 8
        for (int k = 0; k < 64; ++k) {
            float a = As[r][k];
            acc0 = fmaf(a, Ws[og + 0][k], acc0);
            acc1 = fmaf(a, Ws[og + 1][k], acc1);
            acc2 = fmaf(a, Ws[og + 2][k], acc2);
            acc3 = fmaf(a, Ws[og + 3][k], acc3);
        }
        __syncthreads();
    }
    float accs[4] = {acc0, acc1, acc2, acc3};
#pragma unroll
    for (int j = 0; j < 4; ++j) {
        int o = og + j;
        if (o < 16) g_Bm[(size_t)(m0 + r) * STATE + o]        = accs[j] + Bb[o];
        else        g_Cm[(size_t)(m0 + r) * STATE + (o - 16)] = accs[j] + Cb[o - 16];
    }
}

// ---------------- chunked selective scan ----------------
// pass A: per-chunk decay product P and local end-state S (h0 = 0)
// grid (INNER/128, NC, B), block 128
__global__ void __launch_bounds__(128) scanA_kernel(const float* __restrict__ A_log)
{
    __shared__ float sB[LC * STATE];
    const int d = blockIdx.x * 128 + threadIdx.x;
    const int c = blockIdx.y;
    const int b = blockIdx.z;
    const int base_l = c * LC;

    for (int i = threadIdx.x; i < LC * STATE; i += 128)
        sB[i] = g_Bm[(size_t)(b * LEN + base_l) * STATE + i];
    __syncthreads();

    float Ar[STATE];
#pragma unroll
    for (int s = 0; s < STATE; s++) Ar[s] = -expf(A_log[d * STATE + s]);

    float h[STATE], Pr[STATE];
#pragma unroll
    for (int s = 0; s < STATE; s++) { h[s] = 0.f; Pr[s] = 1.f; }

    const float* dtp = g_dt    + (size_t)(b * LEN + base_l) * INNER + d;
    const float* xcp = g_xconv + (size_t)(b * LEN + base_l) * INNER + d;
    for (int l = 0; l < LC; ++l) {
        float dtv = dtp[(size_t)l * INNER];
        float xv  = xcp[(size_t)l * INNER];
        float dtx = dtv * xv;
#pragma unroll
        for (int s = 0; s < STATE; s++) {
            float dA = __expf(dtv * Ar[s]);
            Pr[s] *= dA;
            h[s] = fmaf(dA, h[s], sB[l * STATE + s] * dtx);
        }
    }
    size_t ob = (size_t)(b * NC + c) * STATE * INNER + d;
#pragma unroll
    for (int s = 0; s < STATE; s++) {
        g_P[ob + (size_t)s * INNER] = Pr[s];
        g_S[ob + (size_t)s * INNER] = h[s];
    }
}

// pass B: stitch chunk boundary states. one thread per (b, s, d)
__global__ void __launch_bounds__(256) scanB_kernel()
{
    int g = blockIdx.x * 256 + threadIdx.x;              // 0 .. B*STATE*INNER-1
    int b = g / (STATE * INNER);
    int r = g - b * (STATE * INNER);
    float h = 0.f;
    for (int c = 0; c < NC; ++c) {
        size_t idx = (size_t)(b * NC + c) * STATE * INNER + r;
        g_H0[idx] = h;
        h = g_P[idx] * h + g_S[idx];
    }
}

// pass C: replay with correct h0, produce gated output
// grid (INNER/128, NC, B), block 128
__global__ void __launch_bounds__(128) scanC_kernel(
    const float* __restrict__ A_log, const float* __restrict__ Dv)
{
    __shared__ float sB[LC * STATE];
    __shared__ float sC[LC * STATE];
    const int d = blockIdx.x * 128 + threadIdx.x;
    const int c = blockIdx.y;
    const int b = blockIdx.z;
    const int base_l = c * LC;

    for (int i = threadIdx.x; i < LC * STATE; i += 128) {
        sB[i] = g_Bm[(size_t)(b * LEN + base_l) * STATE + i];
        sC[i] = g_Cm[(size_t)(b * LEN + base_l) * STATE + i];
    }
    __syncthreads();

    float Ar[STATE];
#pragma unroll
    for (int s = 0; s < STATE; s++) Ar[s] = -expf(A_log[d * STATE + s]);
    const float Dd = Dv[d];

    float h[STATE];
    size_t ob = (size_t)(b * NC + c) * STATE * INNER + d;
#pragma unroll
    for (int s = 0; s < STATE; s++) h[s] = g_H0[ob + (size_t)s * INNER];

    const float* dtp = g_dt    + (size_t)(b * LEN + base_l) * INNER + d;
    const float* xcp = g_xconv + (size_t)(b * LEN + base_l) * INNER + d;
    const float* zp  = g_xz    + (size_t)(b * LEN + base_l) * (2 * INNER) + INNER + d;
    float*       yp  = g_y     + (size_t)(b * LEN + base_l) * INNER + d;

    for (int l = 0; l < LC; ++l) {
        float dtv = dtp[(size_t)l * INNER];
        float xv  = xcp[(size_t)l * INNER];
        float zv  = zp[(size_t)l * (2 * INNER)];
        float dtx = dtv * xv;
        float acc = Dd * xv;
#pragma unroll
        for (int s = 0; s < STATE; s++) {
            float dA = __expf(dtv * Ar[s]);
            h[s] = fmaf(dA, h[s], sB[l * STATE + s] * dtx);
            acc  = fmaf(sC[l * STATE + s], h[s], acc);
        }
        yp[(size_t)l * INNER] = acc * siluf(zv);
    }
}

// ---------------- launch ----------------
extern "C" void kernel_launch(void* const* d_in, const int* in_sizes, int n_in,
                              void* d_out, int out_size)
{
    const float* x      = (const float*)d_in[0];
    const float* in_w   = (const float*)d_in[1];
    const float* in_b   = (const float*)d_in[2];
    const float* conv_w = (const float*)d_in[3];
    const float* conv_b = (const float*)d_in[4];
    const float* dt_w   = (const float*)d_in[5];
    const float* dt_b   = (const float*)d_in[6];
    const float* A_log  = (const float*)d_in[7];
    const float* B_w    = (const float*)d_in[8];
    const float* B_b    = (const float*)d_in[9];
    const float* C_w    = (const float*)d_in[10];
    const float* C_b    = (const float*)d_in[11];
    const float* Dv     = (const float*)d_in[12];
    const float* out_w  = (const float*)d_in[13];
    const float* out_b  = (const float*)d_in[14];
    float* out = (float*)d_out;

    float *xz, *xc, *dt, *y;
    cudaGetSymbolAddress((void**)&xz, g_xz);
    cudaGetSymbolAddress((void**)&xc, g_xconv);
    cudaGetSymbolAddress((void**)&dt, g_dt);
    cudaGetSymbolAddress((void**)&y,  g_y);

    // 1) in-proj: xz = x @ in_w^T + in_b          (16384 x 4096 x 1024)
    sgemm_nt<0><<<dim3(4096 / 128, M_TOT / 128), 256>>>(x, in_w, in_b, xz, M_TOT, 4096, HID);

    // 2) causal depthwise conv + silu
    conv_silu_kernel<<<dim3(INNER / 256, LEN / 128, B_SZ), 256>>>(conv_w, conv_b);

    // 3) dt = softplus(xconv @ dt_w^T + dt_b)     (16384 x 2048 x 2048)
    sgemm_nt<1><<<dim3(INNER / 128, M_TOT / 128), 256>>>(xc, dt_w, dt_b, dt, M_TOT, INNER, INNER);

    // 4) B/C projections (N = 32)
    bc_gemm<<<M_TOT / 32, 256>>>(B_w, C_w, B_b, C_b);

    // 5) chunked selective scan + z-gating
    scanA_kernel<<<dim3(INNER / 128, NC, B_SZ), 128>>>(A_log);
    scanB_kernel<<<(B_SZ * STATE * INNER) / 256, 256>>>();
    scanC_kernel<<<dim3(INNER / 128, NC, B_SZ), 128>>>(A_log, Dv);

    // 6) out-proj: out = y @ out_w^T + out_b      (16384 x 1024 x 2048)
    sgemm_nt<0><<<dim3(HID / 128, M_TOT / 128), 256>>>(y, out_w, out_b, out, M_TOT, HID, INNER);
}